// round 1
// baseline (speedup 1.0000x reference)
#include <cuda_runtime.h>

// Problem constants (fixed by the reference):
//   B = 16384 samples, D = 2, G = 2500 grid points.
// Y_surf: [B, D, G] float32 row-major -> per-sample row is 2*2500 contiguous floats.
// For each b: idx = argmin_g (Y_surf[b,0,g]-y[b,0])^2 + (Y_surf[b,1,g]-y[b,1])^2
// Output u[b,d] = U_grid[d, idx]   (U_grid is [D, G]).

#define G_CONST 2500
#define G4_CONST 625            // G / 4, exact (2500 % 4 == 0)
#define WARPS_PER_BLOCK 8

__global__ __launch_bounds__(WARPS_PER_BLOCK * 32)
void lqr_push_kernel(const float* __restrict__ y,
                     const float* __restrict__ Y_surf,
                     const float* __restrict__ U_grid,
                     float* __restrict__ out,
                     int B)
{
    const int warp = threadIdx.x >> 5;
    const int lane = threadIdx.x & 31;
    const int b = blockIdx.x * WARPS_PER_BLOCK + warp;
    if (b >= B) return;

    // Targets for this sample (broadcast within warp via L2/L1; tiny traffic).
    const float y0 = __ldg(&y[2 * b + 0]);
    const float y1 = __ldg(&y[2 * b + 1]);

    // Row base: 16B-aligned because 2500 floats = 10000 bytes (mult. of 16).
    const size_t row = (size_t)b * (size_t)(2 * G_CONST);
    const float4* __restrict__ r0 = reinterpret_cast<const float4*>(Y_surf + row);
    const float4* __restrict__ r1 = reinterpret_cast<const float4*>(Y_surf + row + G_CONST);

    float best = 3.402823466e38f;
    int   bidx = 0;

    // Strided coalesced sweep: lane i touches float4 groups i, i+32, ...
    // Per-iteration: two independent 16B loads -> good MLP; FLOPs are trivial.
    for (int i = lane; i < G4_CONST; i += 32) {
        const float4 a = __ldg(r0 + i);
        const float4 c = __ldg(r1 + i);
        const int gbase = i << 2;

        float dx, dz, d2;

        dx = a.x - y0; dz = c.x - y1; d2 = dx * dx + dz * dz;
        if (d2 < best) { best = d2; bidx = gbase + 0; }

        dx = a.y - y0; dz = c.y - y1; d2 = dx * dx + dz * dz;
        if (d2 < best) { best = d2; bidx = gbase + 1; }

        dx = a.z - y0; dz = c.z - y1; d2 = dx * dx + dz * dz;
        if (d2 < best) { best = d2; bidx = gbase + 2; }

        dx = a.w - y0; dz = c.w - y1; d2 = dx * dx + dz * dz;
        if (d2 < best) { best = d2; bidx = gbase + 3; }
    }
    // Note: within a thread, indices are strictly increasing, so strict '<'
    // keeps the FIRST minimum, matching jnp.argmin.

    // Warp argmin reduction with first-index tie-break.
    #pragma unroll
    for (int off = 16; off > 0; off >>= 1) {
        const float ov = __shfl_xor_sync(0xffffffffu, best, off);
        const int   oi = __shfl_xor_sync(0xffffffffu, bidx, off);
        if (ov < best || (ov == best && oi < bidx)) { best = ov; bidx = oi; }
    }

    if (lane == 0) {
        // U_grid is [D, G] = [2, 2500]; gather column bidx. 20KB table -> L2 hits.
        out[2 * b + 0] = __ldg(&U_grid[bidx]);
        out[2 * b + 1] = __ldg(&U_grid[G_CONST + bidx]);
    }
}

extern "C" void kernel_launch(void* const* d_in, const int* in_sizes, int n_in,
                              void* d_out, int out_size)
{
    const float* y      = (const float*)d_in[0];   // [B, 2]
    const float* Y_surf = (const float*)d_in[1];   // [B, 2, 2500]
    const float* U_grid = (const float*)d_in[2];   // [2, 2500]
    float* out = (float*)d_out;                    // [B, 2]

    const int B = in_sizes[0] / 2;                 // y has B*D elements, D=2

    const int threads = WARPS_PER_BLOCK * 32;      // 256
    const int blocks  = (B + WARPS_PER_BLOCK - 1) / WARPS_PER_BLOCK;

    lqr_push_kernel<<<blocks, threads>>>(y, Y_surf, U_grid, out, B);
}

// round 2
// speedup vs baseline: 1.0379x; 1.0379x over previous
#include <cuda_runtime.h>

// B = 16384 samples, D = 2, G = 2500 grid points.
// Y_surf: [B, 2, 2500] f32.  For each b:
//   idx = argmin_g (Ys[b,0,g]-y[b,0])^2 + (Ys[b,1,g]-y[b,1])^2
//   out[b,d] = U_grid[d, idx]
//
// Layout: ONE warp handles TWO samples (interleaved streams for MLP).
// 8192 warps = 1024 blocks x 256 threads -> single full-chip wave on 148 SMs,
// perfectly balanced (every warp does identical work).

#define G_CONST 2500
#define G4_CONST 625            // G/4 (2500 % 4 == 0; rows are 16B-aligned)
#define WARPS_PER_BLOCK 8

__device__ __forceinline__ void upd(float d2, int g, float& best, int& bidx) {
    // strict '<' keeps FIRST minimum (per-thread indices strictly increase)
    if (d2 < best) { best = d2; bidx = g; }
}

__global__ __launch_bounds__(WARPS_PER_BLOCK * 32, 1)
void lqr_push_kernel2(const float* __restrict__ y,
                      const float* __restrict__ Y_surf,
                      const float* __restrict__ U_grid,
                      float* __restrict__ out,
                      int B)
{
    const int warp = threadIdx.x >> 5;
    const int lane = threadIdx.x & 31;
    const int w    = blockIdx.x * WARPS_PER_BLOCK + warp;

    const int b0 = 2 * w;
    const int b1 = 2 * w + 1;
    if (b0 >= B) return;
    const bool has1 = (b1 < B);          // uniform; B is even in practice

    // Per-sample targets.
    const float y00 = __ldg(&y[2 * b0 + 0]);
    const float y01 = __ldg(&y[2 * b0 + 1]);
    const float y10 = has1 ? __ldg(&y[2 * b1 + 0]) : 0.0f;
    const float y11 = has1 ? __ldg(&y[2 * b1 + 1]) : 0.0f;

    const size_t row0 = (size_t)b0 * (size_t)(2 * G_CONST);
    // if !has1, alias to row0 so loads stay in-bounds; results discarded.
    const size_t row1 = has1 ? (size_t)b1 * (size_t)(2 * G_CONST) : row0;

    const float4* __restrict__ pa = reinterpret_cast<const float4*>(Y_surf + row0);            // s0, d0
    const float4* __restrict__ pb = reinterpret_cast<const float4*>(Y_surf + row0 + G_CONST);  // s0, d1
    const float4* __restrict__ pc = reinterpret_cast<const float4*>(Y_surf + row1);            // s1, d0
    const float4* __restrict__ pd = reinterpret_cast<const float4*>(Y_surf + row1 + G_CONST);  // s1, d1

    float best0 = 3.402823466e38f, best1 = 3.402823466e38f;
    int   idx0 = 0, idx1 = 0;

    // 4 independent 16B streaming loads per iteration; unroll 2 -> 8 in flight.
    #pragma unroll 2
    for (int i = lane; i < G4_CONST; i += 32) {
        const float4 a = __ldcs(pa + i);
        const float4 c = __ldcs(pc + i);
        const float4 bq = __ldcs(pb + i);
        const float4 d = __ldcs(pd + i);
        const int g = i << 2;

        float dx, dz;

        dx = a.x - y00; dz = bq.x - y01; upd(dx*dx + dz*dz, g + 0, best0, idx0);
        dx = a.y - y00; dz = bq.y - y01; upd(dx*dx + dz*dz, g + 1, best0, idx0);
        dx = a.z - y00; dz = bq.z - y01; upd(dx*dx + dz*dz, g + 2, best0, idx0);
        dx = a.w - y00; dz = bq.w - y01; upd(dx*dx + dz*dz, g + 3, best0, idx0);

        dx = c.x - y10; dz = d.x - y11; upd(dx*dx + dz*dz, g + 0, best1, idx1);
        dx = c.y - y10; dz = d.y - y11; upd(dx*dx + dz*dz, g + 1, best1, idx1);
        dx = c.z - y10; dz = d.z - y11; upd(dx*dx + dz*dz, g + 2, best1, idx1);
        dx = c.w - y10; dz = d.w - y11; upd(dx*dx + dz*dz, g + 3, best1, idx1);
    }

    // Warp argmin reduction with first-index tie-break, both samples.
    #pragma unroll
    for (int off = 16; off > 0; off >>= 1) {
        const float ov0 = __shfl_xor_sync(0xffffffffu, best0, off);
        const int   oi0 = __shfl_xor_sync(0xffffffffu, idx0,  off);
        if (ov0 < best0 || (ov0 == best0 && oi0 < idx0)) { best0 = ov0; idx0 = oi0; }

        const float ov1 = __shfl_xor_sync(0xffffffffu, best1, off);
        const int   oi1 = __shfl_xor_sync(0xffffffffu, idx1,  off);
        if (ov1 < best1 || (ov1 == best1 && oi1 < idx1)) { best1 = ov1; idx1 = oi1; }
    }

    if (lane == 0) {
        out[2 * b0 + 0] = __ldg(&U_grid[idx0]);
        out[2 * b0 + 1] = __ldg(&U_grid[G_CONST + idx0]);
        if (has1) {
            out[2 * b1 + 0] = __ldg(&U_grid[idx1]);
            out[2 * b1 + 1] = __ldg(&U_grid[G_CONST + idx1]);
        }
    }
}

extern "C" void kernel_launch(void* const* d_in, const int* in_sizes, int n_in,
                              void* d_out, int out_size)
{
    const float* y      = (const float*)d_in[0];   // [B, 2]
    const float* Y_surf = (const float*)d_in[1];   // [B, 2, 2500]
    const float* U_grid = (const float*)d_in[2];   // [2, 2500]
    float* out = (float*)d_out;                    // [B, 2]

    const int B = in_sizes[0] / 2;

    const int threads = WARPS_PER_BLOCK * 32;                     // 256
    const int pairs   = (B + 1) / 2;                              // samples per warp = 2
    const int blocks  = (pairs + WARPS_PER_BLOCK - 1) / WARPS_PER_BLOCK;  // 1024 for B=16384

    lqr_push_kernel2<<<blocks, threads>>>(y, Y_surf, U_grid, out, B);
}